// round 15
// baseline (speedup 1.0000x reference)
#include <cuda_runtime.h>
#include <cuda_bf16.h>
#include <cstdint>
#include <cstddef>

// Problem constants
#define T_TOK 2048
#define DIMV  512
#define MOE   256
#define NEXP  64
#define NGRP  8
#define TOPG  4
#define TOPK  8
#define CAPE  1024
#define RSCALE 2.5f

#define TM    64                 // token rows per expert tile
#define TILES (CAPE / TM)        // 16
#define NC1   32                 // GEMM1 k-chunks (512/16)
#define NC2   16                 // GEMM2 k-chunks (256/16)

// smem map (SB 1024-aligned):
//   [0,      65536): Xh ; reused after GEMM1 as Hh (32 KB @0) + Hl (32 KB @32768)
//   [65536, 131072): Xl
//   [131072,229376): B stages: 3 x 32 KB, each {hi:16 KB, lo:16 KB}
#define SM_XL  65536u
#define SM_B   131072u
#define SM_BYTES (229376 + 1024)

// ---------------- device scratch (static; no allocations allowed) -----------
__device__ int   g_cnt[NEXP];
__device__ int   g_tok[NEXP * CAPE];
__device__ float g_wt[NEXP * CAPE];

// ---------------- helpers ----------------------------------------------------
__device__ __forceinline__ unsigned su32(const void* p) {
    return (unsigned)__cvta_generic_to_shared(p);
}
__device__ __forceinline__ void ldsm4(uint32_t* r, uint32_t a) {
    asm volatile("ldmatrix.sync.aligned.m8n8.x4.shared.b16 {%0,%1,%2,%3}, [%4];"
        : "=r"(r[0]), "=r"(r[1]), "=r"(r[2]), "=r"(r[3]) : "r"(a));
}
__device__ __forceinline__ void mmabf(float* c, const uint32_t* a, const uint32_t* b) {
    asm volatile("mma.sync.aligned.m16n8k16.row.col.f32.bf16.bf16.f32 "
        "{%0,%1,%2,%3}, {%4,%5,%6,%7}, {%8,%9}, {%0,%1,%2,%3};"
        : "+f"(c[0]), "+f"(c[1]), "+f"(c[2]), "+f"(c[3])
        : "r"(a[0]), "r"(a[1]), "r"(a[2]), "r"(a[3]), "r"(b[0]), "r"(b[1]));
}
#define STS128(a, v0, v1, v2, v3) \
    asm volatile("st.shared.v4.b32 [%0], {%1,%2,%3,%4};" \
        :: "r"(a), "r"(v0), "r"(v1), "r"(v2), "r"(v3) : "memory")

// conflict-free XOR swizzles (granule = 16 B)
__device__ __forceinline__ uint32_t xoff(int row, int kq) {   // 1024 B rows (X)
    return (uint32_t)(row * 1024 + (((kq & ~7) | ((kq ^ row) & 7)) << 4));
}
__device__ __forceinline__ uint32_t hoff(int row, int kq) {   // 512 B rows (H)
    return (uint32_t)(row * 512 + (((kq & ~7) | ((kq ^ row) & 7)) << 4));
}
__device__ __forceinline__ uint32_t boff(int n, int kh) {     // 32 B rows (B)
    return (uint32_t)(n * 32 + ((kh ^ ((n >> 2) & 1)) << 4));
}
__device__ __forceinline__ uint32_t pkbf(float a, float b) {
    __nv_bfloat16 h0 = __float2bfloat16(a), h1 = __float2bfloat16(b);
    return (uint32_t)__bfloat16_as_ushort(h0) |
           ((uint32_t)__bfloat16_as_ushort(h1) << 16);
}

// ---------------------------------------------------------------------------
__global__ void k_init() {
    if (threadIdx.x < NEXP) g_cnt[threadIdx.x] = 0;
}

__global__ void k_zero(float* __restrict__ out) {
    ((float4*)out)[blockIdx.x * 256 + threadIdx.x] =
        make_float4(0.f, 0.f, 0.f, 0.f);
}

// ---------------- gating (unchanged, proven) --------------------------------
__global__ void __launch_bounds__(256) k_gate(const float* __restrict__ x,
                                              const float* __restrict__ gw,
                                              const float* __restrict__ gb) {
    __shared__ float wbuf[8 * DIMV];
    __shared__ float sc[8][NEXP];
    __shared__ float sb[8][NEXP];
    __shared__ float gbs[NEXP];

    int tid = threadIdx.x;
    int w = tid >> 5, lane = tid & 31;
    int t = blockIdx.x * 8 + w;

    if (tid < NEXP) gbs[tid] = gb[tid];

    float xr[16];
#pragma unroll
    for (int i = 0; i < 16; i++) xr[i] = x[(size_t)t * DIMV + lane + 32 * i];

    for (int ec = 0; ec < NEXP / 8; ec++) {
        __syncthreads();
#pragma unroll
        for (int q = 0; q < 16; q++) {
            int idx = q * 256 + tid;
            wbuf[idx] = gw[(size_t)(ec * 8) * DIMV + idx];
        }
        __syncthreads();
#pragma unroll
        for (int j = 0; j < 8; j++) {
            float s = 0.f;
#pragma unroll
            for (int i = 0; i < 16; i++) s += xr[i] * wbuf[j * DIMV + lane + 32 * i];
#pragma unroll
            for (int off = 16; off; off >>= 1) s += __shfl_xor_sync(0xffffffffu, s, off);
            if (lane == 0) sc[w][ec * 8 + j] = 1.f / (1.f + __expf(-s));
        }
    }
    __syncthreads();

    if (lane == 0) {
        float* scw = sc[w];
        float* sbw = sb[w];
        float gs[NGRP];
        for (int g = 0; g < NGRP; g++) {
            float m1 = -1e30f, m2 = -1e30f;
            for (int j = 0; j < 8; j++) {
                float v = scw[g * 8 + j] + gbs[g * 8 + j];
                if (v > m1) { m2 = m1; m1 = v; }
                else if (v > m2) { m2 = v; }
            }
            gs[g] = m1 + m2;
        }
        unsigned allowed = 0;
        for (int p = 0; p < TOPG; p++) {
            float best = -1e30f; int bi = 0;
            for (int g = 0; g < NGRP; g++)
                if (!((allowed >> g) & 1) && gs[g] > best) { best = gs[g]; bi = g; }
            allowed |= 1u << bi;
        }
        for (int e = 0; e < NEXP; e++)
            sbw[e] = ((allowed >> (e >> 3)) & 1) ? scw[e] + gbs[e] : -1e30f;
        int idxs[TOPK]; float wsum = 0.f;
        for (int p = 0; p < TOPK; p++) {
            float best = -1e30f; int bi = 0;
            for (int e = 0; e < NEXP; e++)
                if (sbw[e] > best) { best = sbw[e]; bi = e; }
            idxs[p] = bi; sbw[bi] = -1e30f;
            wsum += scw[bi];
        }
        float inv = RSCALE / wsum;
        for (int p = 0; p < TOPK; p++) {
            int e = idxs[p];
            int pos = atomicAdd(&g_cnt[e], 1);
            if (pos < CAPE) {
                g_tok[e * CAPE + pos] = t;
                g_wt[e * CAPE + pos]  = scw[e] * inv;
            }
        }
    }
}

// ---------------- expert FFN: inline-split bf16 hi/lo 3-pass HMMA -----------
// 8 warps, warp tile 64(m) x 64(n): minimal ldsm bytes per mma (smem-BW bound)
__global__ void __launch_bounds__(256, 1)
k_expert_mma(const float* __restrict__ x,  const float* __restrict__ w1,
             const float* __restrict__ w3, const float* __restrict__ w2,
             float* __restrict__ out) {
    extern __shared__ char smraw[];
    char* SB = (char*)(((uintptr_t)smraw + 1023) & ~(uintptr_t)1023);
    __shared__ int   tok_s[TM];
    __shared__ float wt_s[TM];

    int e    = blockIdx.x >> 4;
    int tile = blockIdx.x & (TILES - 1);
    int tid  = threadIdx.x;
    int wid  = tid >> 5, lane = tid & 31;
    int wn = wid;                             // 1 x 8 warp grid (n only)

    int n = min(g_cnt[e], CAPE);
    int r0g = tile * TM;
    if (r0g >= n) return;                     // uniform over block
    int nr = min(TM, n - r0g);

    if (tid < TM) {
        int ok = tid < nr;
        tok_s[tid] = ok ? g_tok[e * CAPE + r0g + tid] : 0;
        wt_s[tid]  = ok ? g_wt[e * CAPE + r0g + tid]  : 0.f;
    }
    __syncthreads();

    uint32_t sbase = su32(SB);

    // ---- weight prefetch (fp32 -> regs); thread owns n' = {tid, tid+256} ----
    // GEMM1: n' = 2*col + m (m: 0=w1, 1=w3); n'=tid -> col=tid>>1, m=tid&1;
    //        n'=tid+256 -> col = (tid>>1)+128, same m.
    const float* w13base = ((tid & 1) ? w3 : w1) +
                           (size_t)e * 512 * 256 + (tid >> 1);
    auto ldgW1 = [&](int kc, float* r) {
        const float* p = w13base + (size_t)(kc * 16) * 256;
#pragma unroll
        for (int k = 0; k < 16; k++) {
            r[k]      = p[k * 256];
            r[16 + k] = p[k * 256 + 128];
        }
    };
    // GEMM2: n' = d; thread owns d = tid and d = tid+256
    const float* w2base = w2 + (size_t)e * 256 * 512 + tid;
    auto ldgW2 = [&](int kc, float* r) {
        const float* p = w2base + (size_t)(kc * 16) * 512;
#pragma unroll
        for (int k = 0; k < 16; k++) {
            r[k]      = p[k * 512];
            r[16 + k] = p[k * 512 + 256];
        }
    };
    // convert 2 x 16 fp32 (k-runs of rows n'=tid, tid+256) -> hi/lo granules
    auto stW = [&](const float* r, uint32_t stage) {
#pragma unroll
        for (int half = 0; half < 2; half++) {
            uint32_t rowadd = (uint32_t)half * 8192u;   // n' + 256 -> +256*32 B
#pragma unroll
            for (int kh = 0; kh < 2; kh++) {
                uint32_t H[4], L[4];
#pragma unroll
                for (int q = 0; q < 4; q++) {
                    float v0 = r[half * 16 + kh * 8 + q * 2];
                    float v1 = r[half * 16 + kh * 8 + q * 2 + 1];
                    __nv_bfloat16 h0 = __float2bfloat16(v0);
                    __nv_bfloat16 h1 = __float2bfloat16(v1);
                    H[q] = (uint32_t)__bfloat16_as_ushort(h0) |
                           ((uint32_t)__bfloat16_as_ushort(h1) << 16);
                    L[q] = pkbf(v0 - __bfloat162float(h0),
                                v1 - __bfloat162float(h1));
                }
                uint32_t a = stage + rowadd + boff(tid, kh);
                STS128(a,         H[0], H[1], H[2], H[3]);
                STS128(a + 16384, L[0], L[1], L[2], L[3]);
            }
        }
    };

    // ---- Prologue: X fp32 -> bf16 hi/lo smem; W1 chunk 0 staged, 1 in regs --
#pragma unroll
    for (int it = 0; it < 16; it++) {
        int id = it * 256 + tid;                  // 4096 (row, kq) granule slots
        int row = id >> 6, kq = id & 63;
        const float* src = x + (size_t)tok_s[row] * DIMV + kq * 8;
        float v[8];
        *(float4*)(v)     = *(const float4*)(src);
        *(float4*)(v + 4) = *(const float4*)(src + 4);
        uint32_t H[4], L[4];
#pragma unroll
        for (int q = 0; q < 4; q++) {
            __nv_bfloat16 h0 = __float2bfloat16(v[2 * q]);
            __nv_bfloat16 h1 = __float2bfloat16(v[2 * q + 1]);
            H[q] = (uint32_t)__bfloat16_as_ushort(h0) |
                   ((uint32_t)__bfloat16_as_ushort(h1) << 16);
            L[q] = pkbf(v[2 * q]     - __bfloat162float(h0),
                        v[2 * q + 1] - __bfloat162float(h1));
        }
        uint32_t a = xoff(row, kq);
        STS128(sbase + a,         H[0], H[1], H[2], H[3]);
        STS128(sbase + SM_XL + a, L[0], L[1], L[2], L[3]);
    }

    float rgs[32];
    ldgW1(0, rgs);
    stW(rgs, sbase + SM_B + 0 * 32768u);
    ldgW1(1, rgs);
    __syncthreads();                              // X + B stage0 ready

    // lane decompositions
    int lrow = lane & 7, lm = (lane >> 3) & 1, lkh = lane >> 4;   // A ldsm4
    int bN = ((lane >> 4) & 1) * 8 + (lane & 7);                   // B ldsm4 n-offset
    int bKH = (lane >> 3) & 1;                                     // B k-half

    // ================= GEMM1: [64,512] x W13T -> z (n' interleaved) =========
    float acc[4][8][4];
#pragma unroll
    for (int mt = 0; mt < 4; mt++)
#pragma unroll
        for (int j = 0; j < 8; j++)
#pragma unroll
            for (int v = 0; v < 4; v++) acc[mt][j][v] = 0.f;

#pragma unroll 1
    for (int kc = 0; kc < NC1; kc++) {
        // rgs hold W(kc+1); stage (kc+1)%3's old content last read by mma(kc-2)
        if (kc + 1 < NC1) {
            stW(rgs, sbase + SM_B + (uint32_t)((kc + 1) % 3) * 32768u);
            ldgW1(min(kc + 2, NC1 - 1), rgs);
        }
        __syncthreads();

        uint32_t ah[4][4], al[4][4];
#pragma unroll
        for (int mt = 0; mt < 4; mt++) {
            int row = mt * 16 + lrow + lm * 8;
            int kq = kc * 2 + lkh;
            uint32_t off = xoff(row, kq);
            ldsm4(ah[mt], sbase + off);
            ldsm4(al[mt], sbase + SM_XL + off);
        }
        uint32_t bb = sbase + SM_B + (uint32_t)(kc % 3) * 32768u;
#pragma unroll
        for (int j2 = 0; j2 < 4; j2++) {
            int nn = wn * 64 + j2 * 16 + bN;
            uint32_t bo = boff(nn, bKH);
            uint32_t bh[4], bl[4];
            ldsm4(bh, bb + bo);
            ldsm4(bl, bb + 16384 + bo);
#pragma unroll
            for (int mt = 0; mt < 4; mt++) {
                mmabf(acc[mt][2 * j2],     ah[mt], bh);
                mmabf(acc[mt][2 * j2],     al[mt], bh);
                mmabf(acc[mt][2 * j2],     ah[mt], bl);
                mmabf(acc[mt][2 * j2 + 1], ah[mt], bh + 2);
                mmabf(acc[mt][2 * j2 + 1], al[mt], bh + 2);
                mmabf(acc[mt][2 * j2 + 1], ah[mt], bl + 2);
            }
        }
    }
    __syncthreads();                              // all X/B reads done

    // ---- Epilogue 1: (z1,z3) in-register -> h bf16 hi/lo in smem -----------
    // Hh @ SB, Hl @ SB+32768 (reusing Xh region)
#pragma unroll
    for (int mt = 0; mt < 4; mt++) {
        int r1 = mt * 16 + (lane >> 2);
        int r2 = r1 + 8;
#pragma unroll
        for (int j = 0; j < 8; j++) {
            float* c = acc[mt][j];
            int cc = wn * 32 + j * 4 + (lane & 3);     // hidden col
            float h1 = (c[0] * c[1]) / (1.f + __expf(-c[0]));
            float h2 = (c[2] * c[3]) / (1.f + __expf(-c[2]));
            __nv_bfloat16 h1h = __float2bfloat16(h1);
            __nv_bfloat16 h2h = __float2bfloat16(h2);
            int kq = cc >> 3, ci = (cc & 7) * 2;
            *(__nv_bfloat16*)(SB + hoff(r1, kq) + ci) = h1h;
            *(__nv_bfloat16*)(SB + hoff(r2, kq) + ci) = h2h;
            *(__nv_bfloat16*)(SB + 32768 + hoff(r1, kq) + ci) =
                __float2bfloat16(h1 - __bfloat162float(h1h));
            *(__nv_bfloat16*)(SB + 32768 + hoff(r2, kq) + ci) =
                __float2bfloat16(h2 - __bfloat162float(h2h));
        }
    }
    // prologue for GEMM2 weight pipeline (stage0 last read at kc=30; separated
    // by the loop-tail barrier above)
    ldgW2(0, rgs);
    stW(rgs, sbase + SM_B + 0 * 32768u);
    ldgW2(1, rgs);
    __syncthreads();                              // H + B stage0 visible

    // ================= GEMM2: [64,256] x W2T -> Y [64,512] ==================
    float acc2[4][8][4];
#pragma unroll
    for (int mt = 0; mt < 4; mt++)
#pragma unroll
        for (int j = 0; j < 8; j++)
#pragma unroll
            for (int v = 0; v < 4; v++) acc2[mt][j][v] = 0.f;

#pragma unroll 1
    for (int kc = 0; kc < NC2; kc++) {
        if (kc + 1 < NC2) {
            stW(rgs, sbase + SM_B + (uint32_t)((kc + 1) % 3) * 32768u);
            ldgW2(min(kc + 2, NC2 - 1), rgs);
        }
        __syncthreads();

        uint32_t ah[4][4], al[4][4];
#pragma unroll
        for (int mt = 0; mt < 4; mt++) {
            int row = mt * 16 + lrow + lm * 8;
            int kq = kc * 2 + lkh;
            uint32_t off = hoff(row, kq);
            ldsm4(ah[mt], sbase + off);
            ldsm4(al[mt], sbase + 32768 + off);
        }
        uint32_t bb = sbase + SM_B + (uint32_t)(kc % 3) * 32768u;
#pragma unroll
        for (int j2 = 0; j2 < 4; j2++) {
            int nn = wn * 64 + j2 * 16 + bN;
            uint32_t bo = boff(nn, bKH);
            uint32_t bh[4], bl[4];
            ldsm4(bh, bb + bo);
            ldsm4(bl, bb + 16384 + bo);
#pragma unroll
            for (int mt = 0; mt < 4; mt++) {
                mmabf(acc2[mt][2 * j2],     ah[mt], bh);
                mmabf(acc2[mt][2 * j2],     al[mt], bh);
                mmabf(acc2[mt][2 * j2],     ah[mt], bl);
                mmabf(acc2[mt][2 * j2 + 1], ah[mt], bh + 2);
                mmabf(acc2[mt][2 * j2 + 1], al[mt], bh + 2);
                mmabf(acc2[mt][2 * j2 + 1], ah[mt], bl + 2);
            }
        }
    }

    // ---- Epilogue 2: scale rows + atomic accumulate into out ---------------
#pragma unroll
    for (int mt = 0; mt < 4; mt++) {
        int r1 = mt * 16 + (lane >> 2);
        int r2 = r1 + 8;
        float w1s = (r1 < nr) ? wt_s[r1] : 0.f;
        float w2s = (r2 < nr) ? wt_s[r2] : 0.f;
        float* o1 = out + (size_t)tok_s[r1] * DIMV;
        float* o2 = out + (size_t)tok_s[r2] * DIMV;
#pragma unroll
        for (int j = 0; j < 8; j++) {
            float* c = acc2[mt][j];
            int d = wn * 64 + j * 8 + (lane & 3) * 2;
            if (r1 < nr) {
                atomicAdd(o1 + d,     c[0] * w1s);
                atomicAdd(o1 + d + 1, c[1] * w1s);
            }
            if (r2 < nr) {
                atomicAdd(o2 + d,     c[2] * w2s);
                atomicAdd(o2 + d + 1, c[3] * w2s);
            }
        }
    }
}

// ---------------------------------------------------------------------------
extern "C" void kernel_launch(void* const* d_in, const int* in_sizes, int n_in,
                              void* d_out, int out_size) {
    const float* x  = (const float*)d_in[0];
    const float* gw = (const float*)d_in[1];
    const float* gb = (const float*)d_in[2];
    const float* w1 = (const float*)d_in[3];
    const float* w3 = (const float*)d_in[4];
    const float* w2 = (const float*)d_in[5];
    float* out = (float*)d_out;

    (void)in_sizes; (void)n_in; (void)out_size;

    cudaFuncSetAttribute(k_expert_mma, cudaFuncAttributeMaxDynamicSharedMemorySize,
                         SM_BYTES);

    k_init<<<1, 64>>>();
    k_zero<<<(T_TOK * DIMV) / 4 / 256, 256>>>(out);
    k_gate<<<T_TOK / 8, 256>>>(x, gw, gb);
    k_expert_mma<<<NEXP * TILES, 256, SM_BYTES>>>(x, w1, w3, w2, out);
}

// round 16
// speedup vs baseline: 1.3342x; 1.3342x over previous
#include <cuda_runtime.h>
#include <cuda_fp16.h>
#include <cstdint>
#include <cstddef>

// Problem constants
#define T_TOK 2048
#define DIMV  512
#define MOE   256
#define NEXP  64
#define NGRP  8
#define TOPG  4
#define TOPK  8
#define CAPE  1024
#define RSCALE 2.5f

#define TM    64                 // token rows per expert tile
#define TILES (CAPE / TM)        // 16
#define NC1   32                 // GEMM1 k-chunks (512/16)
#define NC2   16                 // GEMM2 k-chunks (256/16)

// smem map (SB 1024-aligned):
//   [0,      65536): Xh ; reused after GEMM1 as Hh (32 KB @0) + Hl (32 KB @32768)
//   [65536, 131072): Xl
//   [131072,180224): B stages: 3 x 16 KB (single fp16 weights)
#define SM_XL  65536u
#define SM_B   131072u
#define SM_BYTES (180224 + 1024)

// ---------------- device scratch (static; no allocations allowed) -----------
__device__ int   g_cnt[NEXP];
__device__ int   g_tok[NEXP * CAPE];
__device__ float g_wt[NEXP * CAPE];

// ---------------- helpers ----------------------------------------------------
__device__ __forceinline__ unsigned su32(const void* p) {
    return (unsigned)__cvta_generic_to_shared(p);
}
__device__ __forceinline__ void ldsm4(uint32_t* r, uint32_t a) {
    asm volatile("ldmatrix.sync.aligned.m8n8.x4.shared.b16 {%0,%1,%2,%3}, [%4];"
        : "=r"(r[0]), "=r"(r[1]), "=r"(r[2]), "=r"(r[3]) : "r"(a));
}
__device__ __forceinline__ void mmahf(float* c, const uint32_t* a, const uint32_t* b) {
    asm volatile("mma.sync.aligned.m16n8k16.row.col.f32.f16.f16.f32 "
        "{%0,%1,%2,%3}, {%4,%5,%6,%7}, {%8,%9}, {%0,%1,%2,%3};"
        : "+f"(c[0]), "+f"(c[1]), "+f"(c[2]), "+f"(c[3])
        : "r"(a[0]), "r"(a[1]), "r"(a[2]), "r"(a[3]), "r"(b[0]), "r"(b[1]));
}
#define STS128(a, v0, v1, v2, v3) \
    asm volatile("st.shared.v4.b32 [%0], {%1,%2,%3,%4};" \
        :: "r"(a), "r"(v0), "r"(v1), "r"(v2), "r"(v3) : "memory")

// conflict-free XOR swizzles (granule = 16 B)
__device__ __forceinline__ uint32_t xoff(int row, int kq) {   // 1024 B rows (X)
    return (uint32_t)(row * 1024 + (((kq & ~7) | ((kq ^ row) & 7)) << 4));
}
__device__ __forceinline__ uint32_t hoff(int row, int kq) {   // 512 B rows (H)
    return (uint32_t)(row * 512 + (((kq & ~7) | ((kq ^ row) & 7)) << 4));
}
__device__ __forceinline__ uint32_t boff(int n, int kh) {     // 32 B rows (B)
    return (uint32_t)(n * 32 + ((kh ^ ((n >> 2) & 1)) << 4));
}
__device__ __forceinline__ uint32_t pkhf(float a, float b) {
    __half h0 = __float2half_rn(a), h1 = __float2half_rn(b);
    return (uint32_t)__half_as_ushort(h0) |
           ((uint32_t)__half_as_ushort(h1) << 16);
}

// ---------------------------------------------------------------------------
__global__ void k_init() {
    if (threadIdx.x < NEXP) g_cnt[threadIdx.x] = 0;
}

__global__ void k_zero(float* __restrict__ out) {
    ((float4*)out)[blockIdx.x * 256 + threadIdx.x] =
        make_float4(0.f, 0.f, 0.f, 0.f);
}

// ---------------- gating (unchanged, proven) --------------------------------
__global__ void __launch_bounds__(256) k_gate(const float* __restrict__ x,
                                              const float* __restrict__ gw,
                                              const float* __restrict__ gb) {
    __shared__ float wbuf[8 * DIMV];
    __shared__ float sc[8][NEXP];
    __shared__ float sb[8][NEXP];
    __shared__ float gbs[NEXP];

    int tid = threadIdx.x;
    int w = tid >> 5, lane = tid & 31;
    int t = blockIdx.x * 8 + w;

    if (tid < NEXP) gbs[tid] = gb[tid];

    float xr[16];
#pragma unroll
    for (int i = 0; i < 16; i++) xr[i] = x[(size_t)t * DIMV + lane + 32 * i];

    for (int ec = 0; ec < NEXP / 8; ec++) {
        __syncthreads();
#pragma unroll
        for (int q = 0; q < 16; q++) {
            int idx = q * 256 + tid;
            wbuf[idx] = gw[(size_t)(ec * 8) * DIMV + idx];
        }
        __syncthreads();
#pragma unroll
        for (int j = 0; j < 8; j++) {
            float s = 0.f;
#pragma unroll
            for (int i = 0; i < 16; i++) s += xr[i] * wbuf[j * DIMV + lane + 32 * i];
#pragma unroll
            for (int off = 16; off; off >>= 1) s += __shfl_xor_sync(0xffffffffu, s, off);
            if (lane == 0) sc[w][ec * 8 + j] = 1.f / (1.f + __expf(-s));
        }
    }
    __syncthreads();

    if (lane == 0) {
        float* scw = sc[w];
        float* sbw = sb[w];
        float gs[NGRP];
        for (int g = 0; g < NGRP; g++) {
            float m1 = -1e30f, m2 = -1e30f;
            for (int j = 0; j < 8; j++) {
                float v = scw[g * 8 + j] + gbs[g * 8 + j];
                if (v > m1) { m2 = m1; m1 = v; }
                else if (v > m2) { m2 = v; }
            }
            gs[g] = m1 + m2;
        }
        unsigned allowed = 0;
        for (int p = 0; p < TOPG; p++) {
            float best = -1e30f; int bi = 0;
            for (int g = 0; g < NGRP; g++)
                if (!((allowed >> g) & 1) && gs[g] > best) { best = gs[g]; bi = g; }
            allowed |= 1u << bi;
        }
        for (int e = 0; e < NEXP; e++)
            sbw[e] = ((allowed >> (e >> 3)) & 1) ? scw[e] + gbs[e] : -1e30f;
        int idxs[TOPK]; float wsum = 0.f;
        for (int p = 0; p < TOPK; p++) {
            float best = -1e30f; int bi = 0;
            for (int e = 0; e < NEXP; e++)
                if (sbw[e] > best) { best = sbw[e]; bi = e; }
            idxs[p] = bi; sbw[bi] = -1e30f;
            wsum += scw[bi];
        }
        float inv = RSCALE / wsum;
        for (int p = 0; p < TOPK; p++) {
            int e = idxs[p];
            int pos = atomicAdd(&g_cnt[e], 1);
            if (pos < CAPE) {
                g_tok[e * CAPE + pos] = t;
                g_wt[e * CAPE + pos]  = scw[e] * inv;
            }
        }
    }
}

// ---------------- expert FFN: fp16 A-hi/lo 2-pass HMMA ----------------------
// Warp grid 2(m) x 8(n), 512 threads (best measured config). A (X, H) split
// into fp16 hi+lo; B (weights) single fp16 -> 2 mma passes per cell.
__global__ void __launch_bounds__(512, 1)
k_expert_mma(const float* __restrict__ x,  const float* __restrict__ w1,
             const float* __restrict__ w3, const float* __restrict__ w2,
             float* __restrict__ out) {
    extern __shared__ char smraw[];
    char* SB = (char*)(((uintptr_t)smraw + 1023) & ~(uintptr_t)1023);
    __shared__ int   tok_s[TM];
    __shared__ float wt_s[TM];

    int e    = blockIdx.x >> 4;
    int tile = blockIdx.x & (TILES - 1);
    int tid  = threadIdx.x;
    int wid  = tid >> 5, lane = tid & 31;
    int wm = wid & 1, wn = wid >> 1;          // 2 x 8 warp grid

    int n = min(g_cnt[e], CAPE);
    int r0g = tile * TM;
    if (r0g >= n) return;                     // uniform over block
    int nr = min(TM, n - r0g);

    if (tid < TM) {
        int ok = tid < nr;
        tok_s[tid] = ok ? g_tok[e * CAPE + r0g + tid] : 0;
        wt_s[tid]  = ok ? g_wt[e * CAPE + r0g + tid]  : 0.f;
    }
    __syncthreads();

    uint32_t sbase = su32(SB);

    // ---- weight prefetch loaders (fp32 -> registers; thread owns n'=tid) ----
    const float* w13base = ((tid & 1) ? w3 : w1) +
                           (size_t)e * 512 * 256 + (tid >> 1);
    auto ldgW1 = [&](int kc, float* r) {
        const float* p = w13base + (size_t)(kc * 16) * 256;
#pragma unroll
        for (int k = 0; k < 16; k++) r[k] = p[k * 256];
    };
    const float* w2base = w2 + (size_t)e * 256 * 512 + tid;
    auto ldgW2 = [&](int kc, float* r) {
        const float* p = w2base + (size_t)(kc * 16) * 512;
#pragma unroll
        for (int k = 0; k < 16; k++) r[k] = p[k * 512];
    };
    // convert 16 fp32 (k-run of row n'=tid) -> single-fp16 granules in stage
    auto stW = [&](const float* r, uint32_t stage) {
#pragma unroll
        for (int kh = 0; kh < 2; kh++) {
            uint32_t H[4];
#pragma unroll
            for (int q = 0; q < 4; q++)
                H[q] = pkhf(r[kh * 8 + q * 2], r[kh * 8 + q * 2 + 1]);
            uint32_t a = stage + boff(tid, kh);
            STS128(a, H[0], H[1], H[2], H[3]);
        }
    };

    // ---- Prologue: X fp32 -> fp16 hi/lo smem; W1 chunk 0 staged, 1 in regs --
#pragma unroll
    for (int it = 0; it < 8; it++) {
        int id = it * 512 + tid;                  // 4096 (row, kq) granule slots
        int row = id >> 6, kq = id & 63;
        const float* src = x + (size_t)tok_s[row] * DIMV + kq * 8;
        float v[8];
        *(float4*)(v)     = *(const float4*)(src);
        *(float4*)(v + 4) = *(const float4*)(src + 4);
        uint32_t H[4], L[4];
#pragma unroll
        for (int q = 0; q < 4; q++) {
            __half h0 = __float2half_rn(v[2 * q]);
            __half h1 = __float2half_rn(v[2 * q + 1]);
            H[q] = (uint32_t)__half_as_ushort(h0) |
                   ((uint32_t)__half_as_ushort(h1) << 16);
            L[q] = pkhf(v[2 * q]     - __half2float(h0),
                        v[2 * q + 1] - __half2float(h1));
        }
        uint32_t a = xoff(row, kq);
        STS128(sbase + a,         H[0], H[1], H[2], H[3]);
        STS128(sbase + SM_XL + a, L[0], L[1], L[2], L[3]);
    }

    float rgs[16];
    ldgW1(0, rgs);
    stW(rgs, sbase + SM_B + 0 * 16384u);
    ldgW1(1, rgs);
    __syncthreads();                              // X + B stage0 ready

    // lane decompositions
    int lrow = lane & 7, lm = (lane >> 3) & 1, lkh = lane >> 4;   // A ldsm4
    int bN = ((lane >> 4) & 1) * 8 + (lane & 7);                   // B ldsm4 n-offset
    int bKH = (lane >> 3) & 1;                                     // B k-half

    // ================= GEMM1: [64,512] x W13T -> z (n' interleaved) =========
    float acc[2][8][4];
#pragma unroll
    for (int mt = 0; mt < 2; mt++)
#pragma unroll
        for (int j = 0; j < 8; j++)
#pragma unroll
            for (int v = 0; v < 4; v++) acc[mt][j][v] = 0.f;

#pragma unroll 1
    for (int kc = 0; kc < NC1; kc++) {
        // rgs hold W(kc+1); stage (kc+1)%3's old content last read by mma(kc-2)
        if (kc + 1 < NC1) {
            stW(rgs, sbase + SM_B + (uint32_t)((kc + 1) % 3) * 16384u);
            ldgW1(min(kc + 2, NC1 - 1), rgs);
        }
        __syncthreads();

        uint32_t ah[2][4], al[2][4];
#pragma unroll
        for (int mt = 0; mt < 2; mt++) {
            int row = wm * 32 + mt * 16 + lrow + lm * 8;
            int kq = kc * 2 + lkh;
            uint32_t off = xoff(row, kq);
            ldsm4(ah[mt], sbase + off);
            ldsm4(al[mt], sbase + SM_XL + off);
        }
        uint32_t bb = sbase + SM_B + (uint32_t)(kc % 3) * 16384u;
#pragma unroll
        for (int j2 = 0; j2 < 4; j2++) {
            int nn = wn * 64 + j2 * 16 + bN;
            uint32_t bo = boff(nn, bKH);
            uint32_t bf[4];
            ldsm4(bf, bb + bo);
#pragma unroll
            for (int mt = 0; mt < 2; mt++) {
                mmahf(acc[mt][2 * j2],     ah[mt], bf);
                mmahf(acc[mt][2 * j2],     al[mt], bf);
                mmahf(acc[mt][2 * j2 + 1], ah[mt], bf + 2);
                mmahf(acc[mt][2 * j2 + 1], al[mt], bf + 2);
            }
        }
    }
    __syncthreads();                              // all X/B reads done

    // ---- Epilogue 1: (z1,z3) in-register -> h fp16 hi/lo in smem -----------
    // Hh @ SB, Hl @ SB+32768 (reusing Xh region)
#pragma unroll
    for (int mt = 0; mt < 2; mt++) {
        int r1 = wm * 32 + mt * 16 + (lane >> 2);
        int r2 = r1 + 8;
#pragma unroll
        for (int j = 0; j < 8; j++) {
            float* c = acc[mt][j];
            int cc = wn * 32 + j * 4 + (lane & 3);     // hidden col
            float h1 = (c[0] * c[1]) / (1.f + __expf(-c[0]));
            float h2 = (c[2] * c[3]) / (1.f + __expf(-c[2]));
            __half h1h = __float2half_rn(h1);
            __half h2h = __float2half_rn(h2);
            int kq = cc >> 3, ci = (cc & 7) * 2;
            *(__half*)(SB + hoff(r1, kq) + ci) = h1h;
            *(__half*)(SB + hoff(r2, kq) + ci) = h2h;
            *(__half*)(SB + 32768 + hoff(r1, kq) + ci) =
                __float2half_rn(h1 - __half2float(h1h));
            *(__half*)(SB + 32768 + hoff(r2, kq) + ci) =
                __float2half_rn(h2 - __half2float(h2h));
        }
    }
    // prologue for GEMM2 weight pipeline (stage0 last read at kc=30; separated
    // by the loop-tail barrier above)
    ldgW2(0, rgs);
    stW(rgs, sbase + SM_B + 0 * 16384u);
    ldgW2(1, rgs);
    __syncthreads();                              // H + B stage0 visible

    // ================= GEMM2: [64,256] x W2T -> Y [64,512] ==================
    float acc2[2][8][4];
#pragma unroll
    for (int mt = 0; mt < 2; mt++)
#pragma unroll
        for (int j = 0; j < 8; j++)
#pragma unroll
            for (int v = 0; v < 4; v++) acc2[mt][j][v] = 0.f;

#pragma unroll 1
    for (int kc = 0; kc < NC2; kc++) {
        if (kc + 1 < NC2) {
            stW(rgs, sbase + SM_B + (uint32_t)((kc + 1) % 3) * 16384u);
            ldgW2(min(kc + 2, NC2 - 1), rgs);
        }
        __syncthreads();

        uint32_t ah[2][4], al[2][4];
#pragma unroll
        for (int mt = 0; mt < 2; mt++) {
            int row = wm * 32 + mt * 16 + lrow + lm * 8;
            int kq = kc * 2 + lkh;
            uint32_t off = hoff(row, kq);
            ldsm4(ah[mt], sbase + off);
            ldsm4(al[mt], sbase + 32768 + off);
        }
        uint32_t bb = sbase + SM_B + (uint32_t)(kc % 3) * 16384u;
#pragma unroll
        for (int j2 = 0; j2 < 4; j2++) {
            int nn = wn * 64 + j2 * 16 + bN;
            uint32_t bo = boff(nn, bKH);
            uint32_t bf[4];
            ldsm4(bf, bb + bo);
#pragma unroll
            for (int mt = 0; mt < 2; mt++) {
                mmahf(acc2[mt][2 * j2],     ah[mt], bf);
                mmahf(acc2[mt][2 * j2],     al[mt], bf);
                mmahf(acc2[mt][2 * j2 + 1], ah[mt], bf + 2);
                mmahf(acc2[mt][2 * j2 + 1], al[mt], bf + 2);
            }
        }
    }

    // ---- Epilogue 2: scale rows + atomic accumulate into out ---------------
#pragma unroll
    for (int mt = 0; mt < 2; mt++) {
        int r1 = wm * 32 + mt * 16 + (lane >> 2);
        int r2 = r1 + 8;
        float w1s = (r1 < nr) ? wt_s[r1] : 0.f;
        float w2s = (r2 < nr) ? wt_s[r2] : 0.f;
        float* o1 = out + (size_t)tok_s[r1] * DIMV;
        float* o2 = out + (size_t)tok_s[r2] * DIMV;
#pragma unroll
        for (int j = 0; j < 8; j++) {
            float* c = acc2[mt][j];
            int d = wn * 64 + j * 8 + (lane & 3) * 2;
            if (r1 < nr) {
                atomicAdd(o1 + d,     c[0] * w1s);
                atomicAdd(o1 + d + 1, c[1] * w1s);
            }
            if (r2 < nr) {
                atomicAdd(o2 + d,     c[2] * w2s);
                atomicAdd(o2 + d + 1, c[3] * w2s);
            }
        }
    }
}

// ---------------------------------------------------------------------------
extern "C" void kernel_launch(void* const* d_in, const int* in_sizes, int n_in,
                              void* d_out, int out_size) {
    const float* x  = (const float*)d_in[0];
    const float* gw = (const float*)d_in[1];
    const float* gb = (const float*)d_in[2];
    const float* w1 = (const float*)d_in[3];
    const float* w3 = (const float*)d_in[4];
    const float* w2 = (const float*)d_in[5];
    float* out = (float*)d_out;

    (void)in_sizes; (void)n_in; (void)out_size;

    cudaFuncSetAttribute(k_expert_mma, cudaFuncAttributeMaxDynamicSharedMemorySize,
                         SM_BYTES);

    k_init<<<1, 64>>>();
    k_zero<<<(T_TOK * DIMV) / 4 / 256, 256>>>(out);
    k_gate<<<T_TOK / 8, 256>>>(x, gw, gb);
    k_expert_mma<<<NEXP * TILES, 512, SM_BYTES>>>(x, w1, w3, w2, out);
}

// round 17
// speedup vs baseline: 1.3964x; 1.0467x over previous
#include <cuda_runtime.h>
#include <cuda_fp16.h>
#include <cstdint>
#include <cstddef>

// Problem constants
#define T_TOK 2048
#define DIMV  512
#define MOE   256
#define NEXP  64
#define NGRP  8
#define TOPG  4
#define TOPK  8
#define CAPE  1024
#define RSCALE 2.5f

#define TM    64                 // token rows per expert tile
#define TILES (CAPE / TM)        // 16
#define NC1   32                 // GEMM1 k-chunks (512/16)
#define NC2   16                 // GEMM2 k-chunks (256/16)

// smem map (SB 1024-aligned):
//   [0,      65536): Xh ; reused after GEMM1 as Hh (32 KB @0) + Hl (32 KB @32768)
//   [65536, 131072): Xl
//   [131072,180224): B stages: 3 x 16 KB, k-major [16 k][512 n' fp16]
#define SM_XL  65536u
#define SM_B   131072u
#define SM_BYTES (180224 + 1024)

// ---------------- device scratch (static; no allocations allowed) -----------
__device__ int   g_cnt[NEXP];
__device__ int   g_tok[NEXP * CAPE];
__device__ float g_wt[NEXP * CAPE];

// ---------------- helpers ----------------------------------------------------
__device__ __forceinline__ unsigned su32(const void* p) {
    return (unsigned)__cvta_generic_to_shared(p);
}
__device__ __forceinline__ void ldsm4(uint32_t* r, uint32_t a) {
    asm volatile("ldmatrix.sync.aligned.m8n8.x4.shared.b16 {%0,%1,%2,%3}, [%4];"
        : "=r"(r[0]), "=r"(r[1]), "=r"(r[2]), "=r"(r[3]) : "r"(a));
}
__device__ __forceinline__ void ldsm4t(uint32_t* r, uint32_t a) {
    asm volatile("ldmatrix.sync.aligned.m8n8.x4.trans.shared.b16 {%0,%1,%2,%3}, [%4];"
        : "=r"(r[0]), "=r"(r[1]), "=r"(r[2]), "=r"(r[3]) : "r"(a));
}
__device__ __forceinline__ void mmahf(float* c, const uint32_t* a, const uint32_t* b) {
    asm volatile("mma.sync.aligned.m16n8k16.row.col.f32.f16.f16.f32 "
        "{%0,%1,%2,%3}, {%4,%5,%6,%7}, {%8,%9}, {%0,%1,%2,%3};"
        : "+f"(c[0]), "+f"(c[1]), "+f"(c[2]), "+f"(c[3])
        : "r"(a[0]), "r"(a[1]), "r"(a[2]), "r"(a[3]), "r"(b[0]), "r"(b[1]));
}
#define STS128(a, v0, v1, v2, v3) \
    asm volatile("st.shared.v4.b32 [%0], {%1,%2,%3,%4};" \
        :: "r"(a), "r"(v0), "r"(v1), "r"(v2), "r"(v3) : "memory")

// conflict-free XOR swizzles (granule = 16 B)
__device__ __forceinline__ uint32_t xoff(int row, int kq) {   // 1024 B rows (X)
    return (uint32_t)(row * 1024 + (((kq & ~7) | ((kq ^ row) & 7)) << 4));
}
__device__ __forceinline__ uint32_t hoff(int row, int kq) {   // 512 B rows (H)
    return (uint32_t)(row * 512 + (((kq & ~7) | ((kq ^ row) & 7)) << 4));
}
// B stage (k-major): row kk (1024 B), granule g = n'>>3, xor-swizzled by kk
__device__ __forceinline__ uint32_t bko(int kk, int g) {
    return (uint32_t)(kk * 1024 + (((g ^ (kk & 7)) & 63) << 4));
}
__device__ __forceinline__ uint32_t pkhf(float a, float b) {
    __half h0 = __float2half_rn(a), h1 = __float2half_rn(b);
    return (uint32_t)__half_as_ushort(h0) |
           ((uint32_t)__half_as_ushort(h1) << 16);
}

// ---------------------------------------------------------------------------
__global__ void k_init() {
    if (threadIdx.x < NEXP) g_cnt[threadIdx.x] = 0;
}

__global__ void k_zero(float* __restrict__ out) {
    ((float4*)out)[blockIdx.x * 256 + threadIdx.x] =
        make_float4(0.f, 0.f, 0.f, 0.f);
}

// ---------------- gating (unchanged, proven) --------------------------------
__global__ void __launch_bounds__(256) k_gate(const float* __restrict__ x,
                                              const float* __restrict__ gw,
                                              const float* __restrict__ gb) {
    __shared__ float wbuf[8 * DIMV];
    __shared__ float sc[8][NEXP];
    __shared__ float sb[8][NEXP];
    __shared__ float gbs[NEXP];

    int tid = threadIdx.x;
    int w = tid >> 5, lane = tid & 31;
    int t = blockIdx.x * 8 + w;

    if (tid < NEXP) gbs[tid] = gb[tid];

    float xr[16];
#pragma unroll
    for (int i = 0; i < 16; i++) xr[i] = x[(size_t)t * DIMV + lane + 32 * i];

    for (int ec = 0; ec < NEXP / 8; ec++) {
        __syncthreads();
#pragma unroll
        for (int q = 0; q < 16; q++) {
            int idx = q * 256 + tid;
            wbuf[idx] = gw[(size_t)(ec * 8) * DIMV + idx];
        }
        __syncthreads();
#pragma unroll
        for (int j = 0; j < 8; j++) {
            float s = 0.f;
#pragma unroll
            for (int i = 0; i < 16; i++) s += xr[i] * wbuf[j * DIMV + lane + 32 * i];
#pragma unroll
            for (int off = 16; off; off >>= 1) s += __shfl_xor_sync(0xffffffffu, s, off);
            if (lane == 0) sc[w][ec * 8 + j] = 1.f / (1.f + __expf(-s));
        }
    }
    __syncthreads();

    if (lane == 0) {
        float* scw = sc[w];
        float* sbw = sb[w];
        float gs[NGRP];
        for (int g = 0; g < NGRP; g++) {
            float m1 = -1e30f, m2 = -1e30f;
            for (int j = 0; j < 8; j++) {
                float v = scw[g * 8 + j] + gbs[g * 8 + j];
                if (v > m1) { m2 = m1; m1 = v; }
                else if (v > m2) { m2 = v; }
            }
            gs[g] = m1 + m2;
        }
        unsigned allowed = 0;
        for (int p = 0; p < TOPG; p++) {
            float best = -1e30f; int bi = 0;
            for (int g = 0; g < NGRP; g++)
                if (!((allowed >> g) & 1) && gs[g] > best) { best = gs[g]; bi = g; }
            allowed |= 1u << bi;
        }
        for (int e = 0; e < NEXP; e++)
            sbw[e] = ((allowed >> (e >> 3)) & 1) ? scw[e] + gbs[e] : -1e30f;
        int idxs[TOPK]; float wsum = 0.f;
        for (int p = 0; p < TOPK; p++) {
            float best = -1e30f; int bi = 0;
            for (int e = 0; e < NEXP; e++)
                if (sbw[e] > best) { best = sbw[e]; bi = e; }
            idxs[p] = bi; sbw[bi] = -1e30f;
            wsum += scw[bi];
        }
        float inv = RSCALE / wsum;
        for (int p = 0; p < TOPK; p++) {
            int e = idxs[p];
            int pos = atomicAdd(&g_cnt[e], 1);
            if (pos < CAPE) {
                g_tok[e * CAPE + pos] = t;
                g_wt[e * CAPE + pos]  = scw[e] * inv;
            }
        }
    }
}

// ---------------- expert FFN: fp16 A-hi/lo 2-pass HMMA ----------------------
// Warp grid 2(m) x 8(n), 512 threads. A (X, H) split into fp16 hi+lo;
// B single fp16, staged k-major + ldmatrix.trans; fully vectorized weight path.
__global__ void __launch_bounds__(512, 1)
k_expert_mma(const float* __restrict__ x,  const float* __restrict__ w1,
             const float* __restrict__ w3, const float* __restrict__ w2,
             float* __restrict__ out) {
    extern __shared__ char smraw[];
    char* SB = (char*)(((uintptr_t)smraw + 1023) & ~(uintptr_t)1023);
    __shared__ int   tok_s[TM];
    __shared__ float wt_s[TM];

    int e    = blockIdx.x >> 4;
    int tile = blockIdx.x & (TILES - 1);
    int tid  = threadIdx.x;
    int wid  = tid >> 5, lane = tid & 31;
    int wm = wid & 1, wn = wid >> 1;          // 2 x 8 warp grid

    int n = min(g_cnt[e], CAPE);
    int r0g = tile * TM;
    if (r0g >= n) return;                     // uniform over block
    int nr = min(TM, n - r0g);

    if (tid < TM) {
        int ok = tid < nr;
        tok_s[tid] = ok ? g_tok[e * CAPE + r0g + tid] : 0;
        wt_s[tid]  = ok ? g_wt[e * CAPE + r0g + tid]  : 0.f;
    }
    __syncthreads();

    uint32_t sbase = su32(SB);

    // ---- vectorized weight loaders ------------------------------------------
    // GEMM1 staging: granule g=q holds n' = 8q..8q+7 = interleaved
    // (w1[c],w3[c],...) for cols c = 4q..4q+3. Thread a-th assignment:
    // id = a*512+tid -> kk = id>>6 (0..15), q = id&63.
    auto ldgW1 = [&](int kc, float* r) {
#pragma unroll
        for (int a = 0; a < 2; a++) {
            int id = a * 512 + tid;
            int kk = id >> 6, q = id & 63;
            size_t off = ((size_t)e * 512 + kc * 16 + kk) * 256 + 4 * q;
            *(float4*)(r + a * 8)     = *(const float4*)(w1 + off);
            *(float4*)(r + a * 8 + 4) = *(const float4*)(w3 + off);
        }
    };
    auto stW1 = [&](const float* r, uint32_t stage) {
#pragma unroll
        for (int a = 0; a < 2; a++) {
            int id = a * 512 + tid;
            int kk = id >> 6, q = id & 63;
            uint32_t H[4];
#pragma unroll
            for (int j = 0; j < 4; j++)
                H[j] = pkhf(r[a * 8 + j], r[a * 8 + 4 + j]);   // (w1[c+j], w3[c+j])
            STS128(stage + bko(kk, q), H[0], H[1], H[2], H[3]);
        }
    };
    // GEMM2 staging: granule q holds n' = d = 8q..8q+7 straight.
    auto ldgW2 = [&](int kc, float* r) {
#pragma unroll
        for (int a = 0; a < 2; a++) {
            int id = a * 512 + tid;
            int kk = id >> 6, q = id & 63;
            const float* p = w2 + ((size_t)e * 256 + kc * 16 + kk) * 512 + 8 * q;
            *(float4*)(r + a * 8)     = *(const float4*)(p);
            *(float4*)(r + a * 8 + 4) = *(const float4*)(p + 4);
        }
    };
    auto stW2 = [&](const float* r, uint32_t stage) {
#pragma unroll
        for (int a = 0; a < 2; a++) {
            int id = a * 512 + tid;
            int kk = id >> 6, q = id & 63;
            uint32_t H[4];
#pragma unroll
            for (int j = 0; j < 4; j++)
                H[j] = pkhf(r[a * 8 + 2 * j], r[a * 8 + 2 * j + 1]);
            STS128(stage + bko(kk, q), H[0], H[1], H[2], H[3]);
        }
    };

    // ---- Prologue: X fp32 -> fp16 hi/lo smem; W1 chunk 0 staged, 1 in regs --
#pragma unroll
    for (int it = 0; it < 8; it++) {
        int id = it * 512 + tid;                  // 4096 (row, kq) granule slots
        int row = id >> 6, kq = id & 63;
        const float* src = x + (size_t)tok_s[row] * DIMV + kq * 8;
        float v[8];
        *(float4*)(v)     = *(const float4*)(src);
        *(float4*)(v + 4) = *(const float4*)(src + 4);
        uint32_t H[4], L[4];
#pragma unroll
        for (int q = 0; q < 4; q++) {
            __half h0 = __float2half_rn(v[2 * q]);
            __half h1 = __float2half_rn(v[2 * q + 1]);
            H[q] = (uint32_t)__half_as_ushort(h0) |
                   ((uint32_t)__half_as_ushort(h1) << 16);
            L[q] = pkhf(v[2 * q]     - __half2float(h0),
                        v[2 * q + 1] - __half2float(h1));
        }
        uint32_t a = xoff(row, kq);
        STS128(sbase + a,         H[0], H[1], H[2], H[3]);
        STS128(sbase + SM_XL + a, L[0], L[1], L[2], L[3]);
    }

    float rgs[16];
    ldgW1(0, rgs);
    stW1(rgs, sbase + SM_B + 0 * 16384u);
    ldgW1(1, rgs);
    __syncthreads();                              // X + B stage0 ready

    // lane decompositions
    int lrow = lane & 7, lm = (lane >> 3) & 1, lkh = lane >> 4;   // A ldsm4
    // B ldsm4.trans: lane -> (k row, granule offset)
    int bkk = (lane & 7) + (((lane >> 3) & 1) << 3);   // k 0..15
    int bgo = (lane >> 4) & 1;                          // +0/+1 granule (8 n')
    uint32_t brow = (uint32_t)(bkk * 1024);
    int bswz = bkk & 7;

    // ================= GEMM1: [64,512] x W13T -> z (n' interleaved) =========
    float acc[2][8][4];
#pragma unroll
    for (int mt = 0; mt < 2; mt++)
#pragma unroll
        for (int j = 0; j < 8; j++)
#pragma unroll
            for (int v = 0; v < 4; v++) acc[mt][j][v] = 0.f;

#pragma unroll 1
    for (int kc = 0; kc < NC1; kc++) {
        // rgs hold W(kc+1); stage (kc+1)%3's old content last read at mma(kc-2)
        if (kc + 1 < NC1) {
            stW1(rgs, sbase + SM_B + (uint32_t)((kc + 1) % 3) * 16384u);
            ldgW1(min(kc + 2, NC1 - 1), rgs);
        }
        __syncthreads();

        uint32_t ah[2][4], al[2][4];
#pragma unroll
        for (int mt = 0; mt < 2; mt++) {
            int row = wm * 32 + mt * 16 + lrow + lm * 8;
            int kq = kc * 2 + lkh;
            uint32_t off = xoff(row, kq);
            ldsm4(ah[mt], sbase + off);
            ldsm4(al[mt], sbase + SM_XL + off);
        }
        uint32_t bb = sbase + SM_B + (uint32_t)(kc % 3) * 16384u;
#pragma unroll
        for (int j2 = 0; j2 < 4; j2++) {
            int gq = wn * 8 + j2 * 2 + bgo;
            uint32_t bf[4];
            ldsm4t(bf, bb + brow + (uint32_t)(((gq ^ bswz) & 63) << 4));
#pragma unroll
            for (int mt = 0; mt < 2; mt++) {
                mmahf(acc[mt][2 * j2],     ah[mt], bf);
                mmahf(acc[mt][2 * j2],     al[mt], bf);
                mmahf(acc[mt][2 * j2 + 1], ah[mt], bf + 2);
                mmahf(acc[mt][2 * j2 + 1], al[mt], bf + 2);
            }
        }
    }
    __syncthreads();                              // all X/B reads done

    // ---- Epilogue 1: (z1,z3) in-register -> h fp16 hi/lo in smem -----------
    // Hh @ SB, Hl @ SB+32768 (reusing Xh region)
#pragma unroll
    for (int mt = 0; mt < 2; mt++) {
        int r1 = wm * 32 + mt * 16 + (lane >> 2);
        int r2 = r1 + 8;
#pragma unroll
        for (int j = 0; j < 8; j++) {
            float* c = acc[mt][j];
            int cc = wn * 32 + j * 4 + (lane & 3);     // hidden col
            float h1 = (c[0] * c[1]) / (1.f + __expf(-c[0]));
            float h2 = (c[2] * c[3]) / (1.f + __expf(-c[2]));
            __half h1h = __float2half_rn(h1);
            __half h2h = __float2half_rn(h2);
            int kq = cc >> 3, ci = (cc & 7) * 2;
            *(__half*)(SB + hoff(r1, kq) + ci) = h1h;
            *(__half*)(SB + hoff(r2, kq) + ci) = h2h;
            *(__half*)(SB + 32768 + hoff(r1, kq) + ci) =
                __float2half_rn(h1 - __half2float(h1h));
            *(__half*)(SB + 32768 + hoff(r2, kq) + ci) =
                __float2half_rn(h2 - __half2float(h2h));
        }
    }
    // prologue for GEMM2 weight pipeline (stage0 last read at kc=30; separated
    // by the loop-tail barrier above)
    ldgW2(0, rgs);
    stW2(rgs, sbase + SM_B + 0 * 16384u);
    ldgW2(1, rgs);
    __syncthreads();                              // H + B stage0 visible

    // ================= GEMM2: [64,256] x W2T -> Y [64,512] ==================
    float acc2[2][8][4];
#pragma unroll
    for (int mt = 0; mt < 2; mt++)
#pragma unroll
        for (int j = 0; j < 8; j++)
#pragma unroll
            for (int v = 0; v < 4; v++) acc2[mt][j][v] = 0.f;

#pragma unroll 1
    for (int kc = 0; kc < NC2; kc++) {
        if (kc + 1 < NC2) {
            stW2(rgs, sbase + SM_B + (uint32_t)((kc + 1) % 3) * 16384u);
            ldgW2(min(kc + 2, NC2 - 1), rgs);
        }
        __syncthreads();

        uint32_t ah[2][4], al[2][4];
#pragma unroll
        for (int mt = 0; mt < 2; mt++) {
            int row = wm * 32 + mt * 16 + lrow + lm * 8;
            int kq = kc * 2 + lkh;
            uint32_t off = hoff(row, kq);
            ldsm4(ah[mt], sbase + off);
            ldsm4(al[mt], sbase + 32768 + off);
        }
        uint32_t bb = sbase + SM_B + (uint32_t)(kc % 3) * 16384u;
#pragma unroll
        for (int j2 = 0; j2 < 4; j2++) {
            int gq = wn * 8 + j2 * 2 + bgo;
            uint32_t bf[4];
            ldsm4t(bf, bb + brow + (uint32_t)(((gq ^ bswz) & 63) << 4));
#pragma unroll
            for (int mt = 0; mt < 2; mt++) {
                mmahf(acc2[mt][2 * j2],     ah[mt], bf);
                mmahf(acc2[mt][2 * j2],     al[mt], bf);
                mmahf(acc2[mt][2 * j2 + 1], ah[mt], bf + 2);
                mmahf(acc2[mt][2 * j2 + 1], al[mt], bf + 2);
            }
        }
    }

    // ---- Epilogue 2: scale rows + atomic accumulate into out ---------------
#pragma unroll
    for (int mt = 0; mt < 2; mt++) {
        int r1 = wm * 32 + mt * 16 + (lane >> 2);
        int r2 = r1 + 8;
        float w1s = (r1 < nr) ? wt_s[r1] : 0.f;
        float w2s = (r2 < nr) ? wt_s[r2] : 0.f;
        float* o1 = out + (size_t)tok_s[r1] * DIMV;
        float* o2 = out + (size_t)tok_s[r2] * DIMV;
#pragma unroll
        for (int j = 0; j < 8; j++) {
            float* c = acc2[mt][j];
            int d = wn * 64 + j * 8 + (lane & 3) * 2;
            if (r1 < nr) {
                atomicAdd(o1 + d,     c[0] * w1s);
                atomicAdd(o1 + d + 1, c[1] * w1s);
            }
            if (r2 < nr) {
                atomicAdd(o2 + d,     c[2] * w2s);
                atomicAdd(o2 + d + 1, c[3] * w2s);
            }
        }
    }
}

// ---------------------------------------------------------------------------
extern "C" void kernel_launch(void* const* d_in, const int* in_sizes, int n_in,
                              void* d_out, int out_size) {
    const float* x  = (const float*)d_in[0];
    const float* gw = (const float*)d_in[1];
    const float* gb = (const float*)d_in[2];
    const float* w1 = (const float*)d_in[3];
    const float* w3 = (const float*)d_in[4];
    const float* w2 = (const float*)d_in[5];
    float* out = (float*)d_out;

    (void)in_sizes; (void)n_in; (void)out_size;

    cudaFuncSetAttribute(k_expert_mma, cudaFuncAttributeMaxDynamicSharedMemorySize,
                         SM_BYTES);

    k_init<<<1, 64>>>();
    k_zero<<<(T_TOK * DIMV) / 4 / 256, 256>>>(out);
    k_gate<<<T_TOK / 8, 256>>>(x, gw, gb);
    k_expert_mma<<<NEXP * TILES, 512, SM_BYTES>>>(x, w1, w3, w2, out);
}